// round 2
// baseline (speedup 1.0000x reference)
#include <cuda_runtime.h>

// Problem constants (fixed by dataset)
#define NN   50000      // nodes
#define INF_ 128        // input features
#define CC   256        // H*HID = 4*64
#define EE   800000     // edges (without self loops)
#define ET   850000     // edges + self loops
#define NSCAN_BLK 196   // ceil(50000/256)

// ---------------- scratch (static device globals; no allocation) -------------
__device__ float  g_h1[NN * CC];      // layer-1 node features (pre-aggregation)
__device__ float  g_out1[NN * CC];    // layer-1 aggregated output
__device__ float4 g_es1[NN];
__device__ float4 g_ed1[NN];
__device__ int    g_deg[NN];
__device__ int    g_incl[NN];
__device__ int    g_rowptr[NN + 1];
__device__ int    g_cnt[NN];
__device__ int    g_bsums[256];
__device__ int    g_ssrc[ET];
__device__ int    g_seid[ET];
__device__ float  g_bnsum[CC], g_bnsq[CC], g_scale[CC], g_shift[CC];
__device__ float2 g_h2[NN];
__device__ float  g_es2[NN], g_ed2[NN];
__device__ int    g_is64;             // edge_index dtype flag (1 = int64, 0 = int32)

__device__ __forceinline__ float lrelu(float x) { return x > 0.f ? x : 0.2f * x; }

// Read edge_index entry `idx` (logical element index in a [2*EE] array),
// handling either int32 or int64 underlying storage.
__device__ __forceinline__ int edge_at(const void* ei, int idx) {
    if (g_is64) return (int)((const long long*)ei)[idx];
    return ((const int*)ei)[idx];
}

// ---------------- dtype detection ----------------
// If data is int64 with small nonnegative values, every odd 32-bit word is 0.
// If data is int32 node ids (uniform in [0,50000)), odd words are ~never all 0.
__global__ void k_detect(const int* __restrict__ w) {
    if (threadIdx.x != 0 || blockIdx.x != 0) return;
    int is64 = 1;
    for (int k = 1; k < 129; k += 2)
        if (w[k] != 0) { is64 = 0; break; }
    g_is64 = is64;
}

// ---------------- zero scratch ----------------
__global__ void k_zero() {
    int i = blockIdx.x * 256 + threadIdx.x;
    if (i < NN) { g_deg[i] = 0; g_cnt[i] = 0; }
    if (i < CC) { g_bnsum[i] = 0.f; g_bnsq[i] = 0.f; }
}

// ---------------- CSR build: histogram / scan / scatter ----------------
__global__ void k_hist(const void* __restrict__ ei) {
    int i = blockIdx.x * 256 + threadIdx.x;
    if (i >= ET) return;
    int d = (i < EE) ? edge_at(ei, EE + i) : (i - EE);
    atomicAdd(&g_deg[d], 1);
}

__global__ void k_scan1() {
    __shared__ int s[256];
    int t = threadIdx.x;
    int i = blockIdx.x * 256 + t;
    int v = (i < NN) ? g_deg[i] : 0;
    s[t] = v;
    __syncthreads();
    for (int off = 1; off < 256; off <<= 1) {
        int tv = (t >= off) ? s[t - off] : 0;
        __syncthreads();
        s[t] += tv;
        __syncthreads();
    }
    if (i < NN) g_incl[i] = s[t];
    if (t == 255) g_bsums[blockIdx.x] = s[255];
}

__global__ void k_scan2() {
    __shared__ int s[256];
    int t = threadIdx.x;
    int v = (t < NSCAN_BLK) ? g_bsums[t] : 0;
    s[t] = v;
    __syncthreads();
    for (int off = 1; off < 256; off <<= 1) {
        int tv = (t >= off) ? s[t - off] : 0;
        __syncthreads();
        s[t] += tv;
        __syncthreads();
    }
    g_bsums[t] = s[t] - v;  // exclusive
}

__global__ void k_scan3() {
    int i = blockIdx.x * 256 + threadIdx.x;
    if (i >= NN) return;
    g_rowptr[i + 1] = g_bsums[blockIdx.x] + g_incl[i];
    if (i == 0) g_rowptr[0] = 0;
}

__global__ void k_scatter(const void* __restrict__ ei) {
    int i = blockIdx.x * 256 + threadIdx.x;
    if (i >= ET) return;
    int s, d;
    if (i < EE) { s = edge_at(ei, i); d = edge_at(ei, EE + i); }
    else        { s = d = i - EE; }
    int pos = g_rowptr[d] + atomicAdd(&g_cnt[d], 1);
    g_ssrc[pos] = s;
    g_seid[pos] = i;
}

// ---------------- GEMM1: h1 = x @ W1  ([N,128]x[128,256]) ----------------
#define BM 128
#define BN 64
#define BK 16
__global__ void k_gemm1(const float* __restrict__ A, const float* __restrict__ B) {
    __shared__ float As[BK][BM + 4];
    __shared__ float Bs[BK][BN + 4];
    int tid = threadIdx.x;
    int bm = blockIdx.x * BM;
    int bn = blockIdx.y * BN;
    int tx = tid & 15;   // 16 col groups * 4
    int ty = tid >> 4;   // 16 row groups * 8
    float acc[8][4];
#pragma unroll
    for (int r = 0; r < 8; r++)
#pragma unroll
        for (int c = 0; c < 4; c++) acc[r][c] = 0.f;

    for (int k0 = 0; k0 < INF_; k0 += BK) {
#pragma unroll
        for (int i = 0; i < 8; i++) {
            int lin = i * 256 + tid;          // 2048 elems, k fastest
            int m = lin >> 4, kk = lin & 15;
            int gr = bm + m;
            float v = 0.f;
            if (gr < NN) v = A[gr * INF_ + k0 + kk];
            As[kk][m] = v;
        }
#pragma unroll
        for (int i = 0; i < 4; i++) {
            int lin = i * 256 + tid;          // 1024 elems, n fastest
            int kk = lin >> 6, nn = lin & 63;
            Bs[kk][nn] = B[(k0 + kk) * CC + bn + nn];
        }
        __syncthreads();
#pragma unroll
        for (int kk = 0; kk < BK; kk++) {
            float4 ra0 = *(const float4*)&As[kk][ty * 8];
            float4 ra1 = *(const float4*)&As[kk][ty * 8 + 4];
            float4 rb  = *(const float4*)&Bs[kk][tx * 4];
            float ra[8] = {ra0.x, ra0.y, ra0.z, ra0.w, ra1.x, ra1.y, ra1.z, ra1.w};
            float rc[4] = {rb.x, rb.y, rb.z, rb.w};
#pragma unroll
            for (int r = 0; r < 8; r++)
#pragma unroll
                for (int c = 0; c < 4; c++) acc[r][c] = fmaf(ra[r], rc[c], acc[r][c]);
        }
        __syncthreads();
    }
#pragma unroll
    for (int r = 0; r < 8; r++) {
        int row = bm + ty * 8 + r;
        if (row < NN) {
#pragma unroll
            for (int c = 0; c < 4; c++) g_h1[row * CC + bn + tx * 4 + c] = acc[r][c];
        }
    }
}

// ---------------- per-node attention logits es/ed (layer 1) ----------------
__global__ void k_esd1(const float* __restrict__ as, const float* __restrict__ ad) {
    int w = (blockIdx.x * blockDim.x + threadIdx.x) >> 5;
    int lane = threadIdx.x & 31;
    if (w >= NN) return;
    const float* hr = &g_h1[(size_t)w * CC];
    float ps[4] = {0, 0, 0, 0}, pd[4] = {0, 0, 0, 0};
#pragma unroll
    for (int j = 0; j < 8; j++) {
        int k = lane + 32 * j;
        float v = hr[k];
        int h = j >> 1;          // (lane+32j)/64
        ps[h] = fmaf(v, as[k], ps[h]);
        pd[h] = fmaf(v, ad[k], pd[h]);
    }
#pragma unroll
    for (int off = 16; off; off >>= 1) {
#pragma unroll
        for (int h = 0; h < 4; h++) {
            ps[h] += __shfl_xor_sync(0xffffffffu, ps[h], off);
            pd[h] += __shfl_xor_sync(0xffffffffu, pd[h], off);
        }
    }
    if (lane == 0) {
        g_es1[w] = make_float4(ps[0], ps[1], ps[2], ps[3]);
        g_ed1[w] = make_float4(pd[0], pd[1], pd[2], pd[3]);
    }
}

// ---------------- layer-1 softmax + aggregation: warp per dst node ----------
__global__ void k_agg1() {
    int n = (blockIdx.x * blockDim.x + threadIdx.x) >> 5;
    int lane = threadIdx.x & 31;
    if (n >= NN) return;
    int r0 = g_rowptr[n], r1 = g_rowptr[n + 1];
    float4 edn = g_ed1[n];
    // pass 1: per-head max (edge-parallel across lanes)
    float m0 = -1e30f, m1 = -1e30f, m2 = -1e30f, m3 = -1e30f;
    for (int j = r0 + lane; j < r1; j += 32) {
        int s = g_ssrc[j];
        float4 es = g_es1[s];
        m0 = fmaxf(m0, lrelu(es.x + edn.x));
        m1 = fmaxf(m1, lrelu(es.y + edn.y));
        m2 = fmaxf(m2, lrelu(es.z + edn.z));
        m3 = fmaxf(m3, lrelu(es.w + edn.w));
    }
#pragma unroll
    for (int off = 16; off; off >>= 1) {
        m0 = fmaxf(m0, __shfl_xor_sync(0xffffffffu, m0, off));
        m1 = fmaxf(m1, __shfl_xor_sync(0xffffffffu, m1, off));
        m2 = fmaxf(m2, __shfl_xor_sync(0xffffffffu, m2, off));
        m3 = fmaxf(m3, __shfl_xor_sync(0xffffffffu, m3, off));
    }
    // pass 2: unnormalized weighted sum; lane owns channels lane+32*j8
    float acc[8] = {0, 0, 0, 0, 0, 0, 0, 0};
    float d0 = 0, d1 = 0, d2 = 0, d3 = 0;
    for (int j = r0; j < r1; ++j) {
        int s = g_ssrc[j];                 // warp-uniform
        float4 es = g_es1[s];
        float p0 = __expf(lrelu(es.x + edn.x) - m0);
        float p1 = __expf(lrelu(es.y + edn.y) - m1);
        float p2 = __expf(lrelu(es.z + edn.z) - m2);
        float p3 = __expf(lrelu(es.w + edn.w) - m3);
        d0 += p0; d1 += p1; d2 += p2; d3 += p3;
        const float* hr = &g_h1[(size_t)s * CC];
#pragma unroll
        for (int j8 = 0; j8 < 8; j8++) {
            float pv = (j8 < 2) ? p0 : (j8 < 4) ? p1 : (j8 < 6) ? p2 : p3;
            acc[j8] = fmaf(pv, hr[lane + 32 * j8], acc[j8]);
        }
    }
    float inv0 = 1.f / (d0 + 1e-16f);
    float inv1 = 1.f / (d1 + 1e-16f);
    float inv2 = 1.f / (d2 + 1e-16f);
    float inv3 = 1.f / (d3 + 1e-16f);
    float* orow = &g_out1[(size_t)n * CC];
#pragma unroll
    for (int j8 = 0; j8 < 8; j8++) {
        float iv = (j8 < 2) ? inv0 : (j8 < 4) ? inv1 : (j8 < 6) ? inv2 : inv3;
        orow[lane + 32 * j8] = acc[j8] * iv;
    }
}

// ---------------- BatchNorm: two-level channel reduction ----------------
#define BN_BLOCKS 200
#define BN_CHUNK  250
__global__ void k_bn_reduce() {
    int c = threadIdx.x;                  // one channel per thread
    int n0 = blockIdx.x * BN_CHUNK;
    int n1 = n0 + BN_CHUNK; if (n1 > NN) n1 = NN;
    float s = 0.f, q = 0.f;
    for (int n = n0; n < n1; n++) {
        float v = g_out1[(size_t)n * CC + c];
        s += v; q += v * v;
    }
    atomicAdd(&g_bnsum[c], s);
    atomicAdd(&g_bnsq[c], q);
}

__global__ void k_bn_final(const float* __restrict__ gamma, const float* __restrict__ beta) {
    int c = threadIdx.x;
    float mean = g_bnsum[c] * (1.f / NN);
    float var = g_bnsq[c] * (1.f / NN) - mean * mean;
    if (var < 0.f) var = 0.f;
    float sc = gamma[c] * rsqrtf(var + 1e-5f);
    g_scale[c] = sc;
    g_shift[c] = beta[c] - mean * sc;
}

// -------- fused BN-apply + ELU + GEMM2 + layer-2 logits : warp per node -----
__global__ void k_l2pre(const float* __restrict__ W2,
                        const float* __restrict__ as2, const float* __restrict__ ad2) {
    int n = (blockIdx.x * blockDim.x + threadIdx.x) >> 5;
    int lane = threadIdx.x & 31;
    if (n >= NN) return;
    const float* orow = &g_out1[(size_t)n * CC];
    const float2* W2v = (const float2*)W2;   // [256] of (w0,w1)
    float a0 = 0.f, a1 = 0.f;
#pragma unroll
    for (int j = 0; j < 8; j++) {
        int k = lane + 32 * j;
        float v = orow[k] * g_scale[k] + g_shift[k];
        v = v > 0.f ? v : expm1f(v);         // ELU
        float2 w = W2v[k];
        a0 = fmaf(v, w.x, a0);
        a1 = fmaf(v, w.y, a1);
    }
#pragma unroll
    for (int off = 16; off; off >>= 1) {
        a0 += __shfl_xor_sync(0xffffffffu, a0, off);
        a1 += __shfl_xor_sync(0xffffffffu, a1, off);
    }
    if (lane == 0) {
        g_h2[n] = make_float2(a0, a1);
        g_es2[n] = a0 * as2[0] + a1 * as2[1];
        g_ed2[n] = a0 * ad2[0] + a1 * ad2[1];
    }
}

// ---------------- layer-2 softmax + aggregation + att output ----------------
__global__ void k_agg2(const float* __restrict__ bias2, float* __restrict__ out) {
    int n = (blockIdx.x * blockDim.x + threadIdx.x) >> 5;
    int lane = threadIdx.x & 31;
    if (n >= NN) return;
    int r0 = g_rowptr[n], r1 = g_rowptr[n + 1];
    float edn = g_ed2[n];
    float m = -1e30f;
    for (int j = r0 + lane; j < r1; j += 32)
        m = fmaxf(m, lrelu(g_es2[g_ssrc[j]] + edn));
#pragma unroll
    for (int off = 16; off; off >>= 1)
        m = fmaxf(m, __shfl_xor_sync(0xffffffffu, m, off));
    float den = 0.f, a0 = 0.f, a1 = 0.f;
    for (int j = r0 + lane; j < r1; j += 32) {
        int s = g_ssrc[j];
        float p = __expf(lrelu(g_es2[s] + edn) - m);
        den += p;
        float2 h = g_h2[s];
        a0 = fmaf(p, h.x, a0);
        a1 = fmaf(p, h.y, a1);
    }
#pragma unroll
    for (int off = 16; off; off >>= 1) {
        den += __shfl_xor_sync(0xffffffffu, den, off);
        a0  += __shfl_xor_sync(0xffffffffu, a0, off);
        a1  += __shfl_xor_sync(0xffffffffu, a1, off);
    }
    float inv = 1.f / (den + 1e-16f);
    for (int j = r0 + lane; j < r1; j += 32) {
        int s = g_ssrc[j];
        float p = __expf(lrelu(g_es2[s] + edn) - m);
        out[2 * NN + g_seid[j]] = p * inv;
    }
    if (lane == 0) {
        out[2 * n]     = a0 * inv + bias2[0];
        out[2 * n + 1] = a1 * inv + bias2[1];
    }
}

// ---------------- launch ----------------
extern "C" void kernel_launch(void* const* d_in, const int* in_sizes, int n_in,
                              void* d_out, int out_size) {
    const float* x     = (const float*)d_in[0];
    const void*  ei    = d_in[1];                 // int32 or int64, autodetected
    const float* W1    = (const float*)d_in[2];
    const float* as1   = (const float*)d_in[3];
    const float* ad1   = (const float*)d_in[4];
    // d_in[5] = bias1 (cancels under batch-norm; skipped)
    const float* gamma = (const float*)d_in[6];
    const float* beta  = (const float*)d_in[7];
    const float* W2    = (const float*)d_in[8];
    const float* as2   = (const float*)d_in[9];
    const float* ad2   = (const float*)d_in[10];
    const float* bias2 = (const float*)d_in[11];
    float*       out   = (float*)d_out;

    // dtype detect + CSR build
    k_detect<<<1, 32>>>((const int*)ei);
    k_zero<<<(NN + 255) / 256, 256>>>();
    k_hist<<<(ET + 255) / 256, 256>>>(ei);
    k_scan1<<<NSCAN_BLK, 256>>>();
    k_scan2<<<1, 256>>>();
    k_scan3<<<NSCAN_BLK, 256>>>();
    k_scatter<<<(ET + 255) / 256, 256>>>(ei);

    // layer 1
    dim3 ggrid((NN + BM - 1) / BM, CC / BN);
    k_gemm1<<<ggrid, 256>>>(x, W1);
    int wgrid = (NN + 7) / 8;  // 8 warps per 256-thread block
    k_esd1<<<wgrid, 256>>>(as1, ad1);
    k_agg1<<<wgrid, 256>>>();

    // batch-norm
    k_bn_reduce<<<BN_BLOCKS, 256>>>();
    k_bn_final<<<1, 256>>>(gamma, beta);

    // layer 2 (fused BN apply + ELU + GEMM2 + logits)
    k_l2pre<<<wgrid, 256>>>(W2, as2, ad2);
    k_agg2<<<wgrid, 256>>>(bias2, out);
}

// round 3
// speedup vs baseline: 1.1239x; 1.1239x over previous
#include <cuda_runtime.h>

// Problem constants (fixed by dataset)
#define NN   50000      // nodes
#define INF_ 128        // input features
#define CC   256        // H*HID = 4*64
#define EE   800000     // edges (without self loops)
#define ET   850000     // edges + self loops
#define NSCAN_BLK 196   // ceil(50000/256)

// ---------------- scratch (static device globals; no allocation) -------------
__device__ float  g_h1[NN * CC];      // layer-1 node features (pre-aggregation)
__device__ float  g_out1[NN * CC];    // layer-1 aggregated output
__device__ float4 g_es1[NN];
__device__ float4 g_ed1[NN];
__device__ int    g_deg[NN];
__device__ int    g_incl[NN];
__device__ int    g_rowptr[NN + 1];
__device__ int    g_cnt[NN];
__device__ int    g_bsums[256];
__device__ int    g_ssrc[ET];
__device__ int    g_seid[ET];
__device__ float  g_bnsum[CC], g_bnsq[CC], g_scale[CC], g_shift[CC];
__device__ float2 g_h2[NN];
__device__ float  g_es2[NN], g_ed2[NN];
__device__ int    g_is64;             // edge_index dtype flag

__device__ __forceinline__ float lrelu(float x) { return x > 0.f ? x : 0.2f * x; }

__device__ __forceinline__ int edge_at(const void* ei, int idx) {
    if (g_is64) return (int)((const long long*)ei)[idx];
    return ((const int*)ei)[idx];
}

// ---------------- dtype detection ----------------
__global__ void k_detect(const int* __restrict__ w) {
    if (threadIdx.x != 0 || blockIdx.x != 0) return;
    int is64 = 1;
    for (int k = 1; k < 129; k += 2)
        if (w[k] != 0) { is64 = 0; break; }
    g_is64 = is64;
}

// ---------------- zero scratch ----------------
__global__ void k_zero() {
    int i = blockIdx.x * 256 + threadIdx.x;
    if (i < NN) { g_deg[i] = 0; g_cnt[i] = 0; }
    if (i < CC) { g_bnsum[i] = 0.f; g_bnsq[i] = 0.f; }
}

// ---------------- CSR build ----------------
__global__ void k_hist(const void* __restrict__ ei) {
    int i = blockIdx.x * 256 + threadIdx.x;
    if (i >= ET) return;
    int d = (i < EE) ? edge_at(ei, EE + i) : (i - EE);
    atomicAdd(&g_deg[d], 1);
}

__global__ void k_scan1() {
    __shared__ int s[256];
    int t = threadIdx.x;
    int i = blockIdx.x * 256 + t;
    int v = (i < NN) ? g_deg[i] : 0;
    s[t] = v;
    __syncthreads();
    for (int off = 1; off < 256; off <<= 1) {
        int tv = (t >= off) ? s[t - off] : 0;
        __syncthreads();
        s[t] += tv;
        __syncthreads();
    }
    if (i < NN) g_incl[i] = s[t];
    if (t == 255) g_bsums[blockIdx.x] = s[255];
}

__global__ void k_scan2() {
    __shared__ int s[256];
    int t = threadIdx.x;
    int v = (t < NSCAN_BLK) ? g_bsums[t] : 0;
    s[t] = v;
    __syncthreads();
    for (int off = 1; off < 256; off <<= 1) {
        int tv = (t >= off) ? s[t - off] : 0;
        __syncthreads();
        s[t] += tv;
        __syncthreads();
    }
    g_bsums[t] = s[t] - v;  // exclusive
}

__global__ void k_scan3() {
    int i = blockIdx.x * 256 + threadIdx.x;
    if (i >= NN) return;
    g_rowptr[i + 1] = g_bsums[blockIdx.x] + g_incl[i];
    if (i == 0) g_rowptr[0] = 0;
}

__global__ void k_scatter(const void* __restrict__ ei) {
    int i = blockIdx.x * 256 + threadIdx.x;
    if (i >= ET) return;
    int s, d;
    if (i < EE) { s = edge_at(ei, i); d = edge_at(ei, EE + i); }
    else        { s = d = i - EE; }
    int pos = g_rowptr[d] + atomicAdd(&g_cnt[d], 1);
    g_ssrc[pos] = s;
    g_seid[pos] = i;
}

// ---------------- GEMM1: 3xTF32 tensor-core  h1 = x @ W1 ----------------
#define GM 128
#define GN 64
#define GK 16
#define ASTR 20     // A smem k-stride (words)
#define BSTR 72     // B smem n-stride (words)

__device__ __forceinline__ unsigned tf32_of(float x) {
    unsigned r;
    asm("cvt.rna.tf32.f32 %0, %1;" : "=r"(r) : "f"(x));
    return r;
}
__device__ __forceinline__ void split_tf32(float x, unsigned& h, unsigned& l) {
    h = tf32_of(x);
    l = tf32_of(x - __uint_as_float(h));
}
__device__ __forceinline__ void mma_tf32(float* c, const unsigned* a,
                                         unsigned b0, unsigned b1) {
    asm volatile(
        "mma.sync.aligned.m16n8k8.row.col.f32.tf32.tf32.f32 "
        "{%0,%1,%2,%3}, {%4,%5,%6,%7}, {%8,%9}, {%0,%1,%2,%3};"
        : "+f"(c[0]), "+f"(c[1]), "+f"(c[2]), "+f"(c[3])
        : "r"(a[0]), "r"(a[1]), "r"(a[2]), "r"(a[3]), "r"(b0), "r"(b1));
}

__global__ __launch_bounds__(256) void k_gemm1(const float* __restrict__ A,
                                               const float* __restrict__ B) {
    __shared__ unsigned Ah[GM * ASTR], Al[GM * ASTR];
    __shared__ unsigned Bh[GK * BSTR], Bl[GK * BSTR];
    int tid = threadIdx.x;
    int bm = blockIdx.x * GM, bn = blockIdx.y * GN;
    int wid = tid >> 5, lane = tid & 31;
    int wm = wid & 3, wn = wid >> 2;          // 4x2 warp grid, warp tile 32x32
    int g = lane >> 2, tg = lane & 3;

    float acc[2][4][4];
#pragma unroll
    for (int mi = 0; mi < 2; mi++)
#pragma unroll
        for (int ni = 0; ni < 4; ni++)
#pragma unroll
            for (int c = 0; c < 4; c++) acc[mi][ni][c] = 0.f;

    for (int k0 = 0; k0 < INF_; k0 += GK) {
        // fill A tile: 128 rows x 16 k ; 2 float4 per thread
#pragma unroll
        for (int i = 0; i < 2; i++) {
            int v = tid + i * 256;
            int row = v >> 2, kc = (v & 3) * 4;
            float4 val = make_float4(0.f, 0.f, 0.f, 0.f);
            if (bm + row < NN)
                val = *(const float4*)&A[(size_t)(bm + row) * INF_ + k0 + kc];
            unsigned h, l;
            int base = row * ASTR + kc;
            split_tf32(val.x, h, l); Ah[base]     = h; Al[base]     = l;
            split_tf32(val.y, h, l); Ah[base + 1] = h; Al[base + 1] = l;
            split_tf32(val.z, h, l); Ah[base + 2] = h; Al[base + 2] = l;
            split_tf32(val.w, h, l); Ah[base + 3] = h; Al[base + 3] = l;
        }
        // fill B tile: 16 k x 64 n ; 1 float4 per thread
        {
            int kk = tid >> 4, nc = (tid & 15) * 4;
            float4 val = *(const float4*)&B[(size_t)(k0 + kk) * CC + bn + nc];
            unsigned h, l;
            int base = kk * BSTR + nc;
            split_tf32(val.x, h, l); Bh[base]     = h; Bl[base]     = l;
            split_tf32(val.y, h, l); Bh[base + 1] = h; Bl[base + 1] = l;
            split_tf32(val.z, h, l); Bh[base + 2] = h; Bl[base + 2] = l;
            split_tf32(val.w, h, l); Bh[base + 3] = h; Bl[base + 3] = l;
        }
        __syncthreads();

#pragma unroll
        for (int ks = 0; ks < 2; ks++) {
            int kb = ks * 8;
            unsigned ah[2][4], al[2][4];
#pragma unroll
            for (int mi = 0; mi < 2; mi++) {
                int R = wm * 32 + mi * 16;
                int b0 = (R + g) * ASTR + kb + tg;
                int b1 = (R + 8 + g) * ASTR + kb + tg;
                ah[mi][0] = Ah[b0]; ah[mi][1] = Ah[b1];
                ah[mi][2] = Ah[b0 + 4]; ah[mi][3] = Ah[b1 + 4];
                al[mi][0] = Al[b0]; al[mi][1] = Al[b1];
                al[mi][2] = Al[b0 + 4]; al[mi][3] = Al[b1 + 4];
            }
#pragma unroll
            for (int ni = 0; ni < 4; ni++) {
                int C = wn * 32 + ni * 8;
                int i0 = (kb + tg) * BSTR + C + g;
                int i1 = (kb + 4 + tg) * BSTR + C + g;
                unsigned bh0 = Bh[i0], bh1 = Bh[i1];
                unsigned bl0 = Bl[i0], bl1 = Bl[i1];
#pragma unroll
                for (int mi = 0; mi < 2; mi++) {
                    mma_tf32(acc[mi][ni], al[mi], bh0, bh1);
                    mma_tf32(acc[mi][ni], ah[mi], bl0, bl1);
                    mma_tf32(acc[mi][ni], ah[mi], bh0, bh1);
                }
            }
        }
        __syncthreads();
    }
    // epilogue
#pragma unroll
    for (int mi = 0; mi < 2; mi++) {
        int row0 = bm + wm * 32 + mi * 16 + g;
#pragma unroll
        for (int ni = 0; ni < 4; ni++) {
            int col = bn + wn * 32 + ni * 8 + 2 * tg;
            if (row0 < NN)
                *(float2*)&g_h1[(size_t)row0 * CC + col] =
                    make_float2(acc[mi][ni][0], acc[mi][ni][1]);
            if (row0 + 8 < NN)
                *(float2*)&g_h1[(size_t)(row0 + 8) * CC + col] =
                    make_float2(acc[mi][ni][2], acc[mi][ni][3]);
        }
    }
}

// ---------------- per-node attention logits es/ed (layer 1) ----------------
__global__ void k_esd1(const float* __restrict__ as, const float* __restrict__ ad) {
    int n = (blockIdx.x * blockDim.x + threadIdx.x) >> 5;
    int lane = threadIdx.x & 31;
    if (n >= NN) return;
    const float4* hr = (const float4*)&g_h1[(size_t)n * CC];
    const float4* as4 = (const float4*)as;
    const float4* ad4 = (const float4*)ad;
    float4 vA = hr[lane], vB = hr[32 + lane];
    float4 aA = as4[lane], aB = as4[32 + lane];
    float4 dA = ad4[lane], dB = ad4[32 + lane];
    float sA = vA.x * aA.x + vA.y * aA.y + vA.z * aA.z + vA.w * aA.w;
    float sB = vB.x * aB.x + vB.y * aB.y + vB.z * aB.z + vB.w * aB.w;
    float tA = vA.x * dA.x + vA.y * dA.y + vA.z * dA.z + vA.w * dA.w;
    float tB = vB.x * dB.x + vB.y * dB.y + vB.z * dB.z + vB.w * dB.w;
#pragma unroll
    for (int off = 8; off; off >>= 1) {
        sA += __shfl_xor_sync(0xffffffffu, sA, off);
        sB += __shfl_xor_sync(0xffffffffu, sB, off);
        tA += __shfl_xor_sync(0xffffffffu, tA, off);
        tB += __shfl_xor_sync(0xffffffffu, tB, off);
    }
    // lane0: heads 0 (sA), 2 (sB); lane16: heads 1 (sA), 3 (sB)
    float sA16 = __shfl_sync(0xffffffffu, sA, 16);
    float sB16 = __shfl_sync(0xffffffffu, sB, 16);
    float tA16 = __shfl_sync(0xffffffffu, tA, 16);
    float tB16 = __shfl_sync(0xffffffffu, tB, 16);
    if (lane == 0) {
        g_es1[n] = make_float4(sA, sA16, sB, sB16);
        g_ed1[n] = make_float4(tA, tA16, tB, tB16);
    }
}

// ---------------- layer-1 softmax + aggregation: warp per dst node ----------
__global__ void k_agg1() {
    int n = (blockIdx.x * blockDim.x + threadIdx.x) >> 5;
    int lane = threadIdx.x & 31;
    if (n >= NN) return;
    int r0 = g_rowptr[n], r1 = g_rowptr[n + 1];
    float4 edn = g_ed1[n];
    // pass 1: per-head max (edge-parallel across lanes)
    float m0 = -1e30f, m1 = -1e30f, m2 = -1e30f, m3 = -1e30f;
    for (int j = r0 + lane; j < r1; j += 32) {
        int s = g_ssrc[j];
        float4 es = g_es1[s];
        m0 = fmaxf(m0, lrelu(es.x + edn.x));
        m1 = fmaxf(m1, lrelu(es.y + edn.y));
        m2 = fmaxf(m2, lrelu(es.z + edn.z));
        m3 = fmaxf(m3, lrelu(es.w + edn.w));
    }
#pragma unroll
    for (int off = 16; off; off >>= 1) {
        m0 = fmaxf(m0, __shfl_xor_sync(0xffffffffu, m0, off));
        m1 = fmaxf(m1, __shfl_xor_sync(0xffffffffu, m1, off));
        m2 = fmaxf(m2, __shfl_xor_sync(0xffffffffu, m2, off));
        m3 = fmaxf(m3, __shfl_xor_sync(0xffffffffu, m3, off));
    }
    // pass 2: unnormalized weighted sum; lane owns channels 4*lane.. / 128+4*lane..
    float4 accA = make_float4(0.f, 0.f, 0.f, 0.f);
    float4 accB = make_float4(0.f, 0.f, 0.f, 0.f);
    float d0 = 0.f, d1 = 0.f, d2 = 0.f, d3 = 0.f;
    for (int j = r0; j < r1; ++j) {
        int s = g_ssrc[j];                 // warp-uniform
        float4 es = g_es1[s];
        float p0 = __expf(lrelu(es.x + edn.x) - m0);
        float p1 = __expf(lrelu(es.y + edn.y) - m1);
        float p2 = __expf(lrelu(es.z + edn.z) - m2);
        float p3 = __expf(lrelu(es.w + edn.w) - m3);
        d0 += p0; d1 += p1; d2 += p2; d3 += p3;
        const float4* hr = (const float4*)&g_h1[(size_t)s * CC];
        float4 hA = hr[lane];        // channels 4*lane..   heads 0/1
        float4 hB = hr[32 + lane];   // channels 128+4*lane heads 2/3
        float pA = lane < 16 ? p0 : p1;
        float pB = lane < 16 ? p2 : p3;
        accA.x = fmaf(pA, hA.x, accA.x); accA.y = fmaf(pA, hA.y, accA.y);
        accA.z = fmaf(pA, hA.z, accA.z); accA.w = fmaf(pA, hA.w, accA.w);
        accB.x = fmaf(pB, hB.x, accB.x); accB.y = fmaf(pB, hB.y, accB.y);
        accB.z = fmaf(pB, hB.z, accB.z); accB.w = fmaf(pB, hB.w, accB.w);
    }
    float inv0 = 1.f / (d0 + 1e-16f);
    float inv1 = 1.f / (d1 + 1e-16f);
    float inv2 = 1.f / (d2 + 1e-16f);
    float inv3 = 1.f / (d3 + 1e-16f);
    float invA = lane < 16 ? inv0 : inv1;
    float invB = lane < 16 ? inv2 : inv3;
    float4* orow = (float4*)&g_out1[(size_t)n * CC];
    orow[lane]      = make_float4(accA.x * invA, accA.y * invA, accA.z * invA, accA.w * invA);
    orow[32 + lane] = make_float4(accB.x * invB, accB.y * invB, accB.z * invB, accB.w * invB);
}

// ---------------- BatchNorm: two-level channel reduction ----------------
#define BN_BLOCKS 200
#define BN_CHUNK  250
__global__ void k_bn_reduce() {
    int c = threadIdx.x;
    int n0 = blockIdx.x * BN_CHUNK;
    int n1 = n0 + BN_CHUNK; if (n1 > NN) n1 = NN;
    float s = 0.f, q = 0.f;
    for (int n = n0; n < n1; n++) {
        float v = g_out1[(size_t)n * CC + c];
        s += v; q += v * v;
    }
    atomicAdd(&g_bnsum[c], s);
    atomicAdd(&g_bnsq[c], q);
}

__global__ void k_bn_final(const float* __restrict__ gamma, const float* __restrict__ beta) {
    int c = threadIdx.x;
    float mean = g_bnsum[c] * (1.f / NN);
    float var = g_bnsq[c] * (1.f / NN) - mean * mean;
    if (var < 0.f) var = 0.f;
    float sc = gamma[c] * rsqrtf(var + 1e-5f);
    g_scale[c] = sc;
    g_shift[c] = beta[c] - mean * sc;
}

// -------- fused BN-apply + ELU + GEMM2 + layer-2 logits : warp per node -----
__global__ void k_l2pre(const float* __restrict__ W2,
                        const float* __restrict__ as2, const float* __restrict__ ad2) {
    int n = (blockIdx.x * blockDim.x + threadIdx.x) >> 5;
    int lane = threadIdx.x & 31;
    if (n >= NN) return;
    const float4* orow = (const float4*)&g_out1[(size_t)n * CC];
    const float4* sc4 = (const float4*)g_scale;
    const float4* sh4 = (const float4*)g_shift;
    const float2* W2v = (const float2*)W2;   // [256] of (w0,w1)
    float a0 = 0.f, a1 = 0.f;
#pragma unroll
    for (int half = 0; half < 2; half++) {
        int idx = half * 32 + lane;
        float4 o = orow[idx];
        float4 sc = sc4[idx];
        float4 sh = sh4[idx];
        float v[4] = {o.x * sc.x + sh.x, o.y * sc.y + sh.y,
                      o.z * sc.z + sh.z, o.w * sc.w + sh.w};
#pragma unroll
        for (int i = 0; i < 4; i++) {
            float vv = v[i] > 0.f ? v[i] : expm1f(v[i]);
            float2 w = W2v[idx * 4 + i];
            a0 = fmaf(vv, w.x, a0);
            a1 = fmaf(vv, w.y, a1);
        }
    }
#pragma unroll
    for (int off = 16; off; off >>= 1) {
        a0 += __shfl_xor_sync(0xffffffffu, a0, off);
        a1 += __shfl_xor_sync(0xffffffffu, a1, off);
    }
    if (lane == 0) {
        g_h2[n] = make_float2(a0, a1);
        g_es2[n] = a0 * as2[0] + a1 * as2[1];
        g_ed2[n] = a0 * ad2[0] + a1 * ad2[1];
    }
}

// ---------------- layer-2 softmax + aggregation + att output ----------------
__global__ void k_agg2(const float* __restrict__ bias2, float* __restrict__ out) {
    int n = (blockIdx.x * blockDim.x + threadIdx.x) >> 5;
    int lane = threadIdx.x & 31;
    if (n >= NN) return;
    int r0 = g_rowptr[n], r1 = g_rowptr[n + 1];
    float edn = g_ed2[n];
    float m = -1e30f;
    for (int j = r0 + lane; j < r1; j += 32)
        m = fmaxf(m, lrelu(g_es2[g_ssrc[j]] + edn));
#pragma unroll
    for (int off = 16; off; off >>= 1)
        m = fmaxf(m, __shfl_xor_sync(0xffffffffu, m, off));
    float den = 0.f, a0 = 0.f, a1 = 0.f;
    for (int j = r0 + lane; j < r1; j += 32) {
        int s = g_ssrc[j];
        float p = __expf(lrelu(g_es2[s] + edn) - m);
        den += p;
        float2 h = g_h2[s];
        a0 = fmaf(p, h.x, a0);
        a1 = fmaf(p, h.y, a1);
    }
#pragma unroll
    for (int off = 16; off; off >>= 1) {
        den += __shfl_xor_sync(0xffffffffu, den, off);
        a0  += __shfl_xor_sync(0xffffffffu, a0, off);
        a1  += __shfl_xor_sync(0xffffffffu, a1, off);
    }
    float inv = 1.f / (den + 1e-16f);
    for (int j = r0 + lane; j < r1; j += 32) {
        int s = g_ssrc[j];
        float p = __expf(lrelu(g_es2[s] + edn) - m);
        out[2 * NN + g_seid[j]] = p * inv;
    }
    if (lane == 0) {
        out[2 * n]     = a0 * inv + bias2[0];
        out[2 * n + 1] = a1 * inv + bias2[1];
    }
}

// ---------------- launch ----------------
extern "C" void kernel_launch(void* const* d_in, const int* in_sizes, int n_in,
                              void* d_out, int out_size) {
    const float* x     = (const float*)d_in[0];
    const void*  ei    = d_in[1];                 // int32 or int64, autodetected
    const float* W1    = (const float*)d_in[2];
    const float* as1   = (const float*)d_in[3];
    const float* ad1   = (const float*)d_in[4];
    // d_in[5] = bias1 (cancels under batch-norm; skipped)
    const float* gamma = (const float*)d_in[6];
    const float* beta  = (const float*)d_in[7];
    const float* W2    = (const float*)d_in[8];
    const float* as2   = (const float*)d_in[9];
    const float* ad2   = (const float*)d_in[10];
    const float* bias2 = (const float*)d_in[11];
    float*       out   = (float*)d_out;

    // dtype detect + CSR build
    k_detect<<<1, 32>>>((const int*)ei);
    k_zero<<<(NN + 255) / 256, 256>>>();
    k_hist<<<(ET + 255) / 256, 256>>>(ei);
    k_scan1<<<NSCAN_BLK, 256>>>();
    k_scan2<<<1, 256>>>();
    k_scan3<<<NSCAN_BLK, 256>>>();
    k_scatter<<<(ET + 255) / 256, 256>>>(ei);

    // layer 1
    dim3 ggrid((NN + GM - 1) / GM, CC / GN);
    k_gemm1<<<ggrid, 256>>>(x, W1);
    int wgrid = (NN + 7) / 8;  // 8 warps per 256-thread block
    k_esd1<<<wgrid, 256>>>(as1, ad1);
    k_agg1<<<wgrid, 256>>>();

    // batch-norm
    k_bn_reduce<<<BN_BLOCKS, 256>>>();
    k_bn_final<<<1, 256>>>(gamma, beta);

    // layer 2 (fused BN apply + ELU + GEMM2 + logits)
    k_l2pre<<<wgrid, 256>>>(W2, as2, ad2);
    k_agg2<<<wgrid, 256>>>(bias2, out);
}